// round 13
// baseline (speedup 1.0000x reference)
#include <cuda_runtime.h>
#include <cstdint>
#include <cstddef>

// Problem constants
#define NB   8
#define CB   128
#define NC   1024          // NB*CB
#define HH   160
#define WW   160
#define NA   180
#define NR   180
#define AR   (NA*NR)       // 32400
#define PIX  (HH*WW)       // 25600
#define WR   16            // staged rho-window rows (16x8 tile span <= 14)
#define PH   3             // angles per staging phase
#define NPHASE (NA/PH)     // 60
#define TPB  256
#define BUFB (PH*WR*512)   // 24576 B per buffer

// Scratch in __device__ globals (no allocation allowed)
__device__ float         g_T[(size_t)AR * NC];       // transposed: T[a][r][nc]
__device__ unsigned char g_idx[(size_t)NA * PIX];    // r index table [a][y][x]
__device__ double        g_tab[2 * NA];              // cos/irho, sin/irho

// ---- sorted 4x4-block walk orders (px = x + 4y), by tan-theta class ----
#define ORD_Q0 0,4,8,12,1,5,9,13,2,6,10,14,3,7,11,15
#define ORD_Q1 0,4,8,1,12,5,9,2,13,6,10,3,14,7,11,15
#define ORD_Q2 0,4,1,8,5,12,2,9,6,13,3,10,7,14,11,15
#define ORD_Q3 0,4,1,8,5,2,12,9,6,3,13,10,7,14,11,15
#define ORD_Q4 0,1,4,2,5,8,3,6,9,12,7,10,13,11,14,15
#define ORD_Q5 0,1,4,2,5,3,8,6,9,7,12,10,13,11,14,15
#define ORD_Q6 0,1,2,4,3,5,6,8,7,9,10,12,11,13,14,15
#define ORD_Q7 0,1,2,3,4,5,6,7,8,9,10,11,12,13,14,15

#define PK(A,B,C,D,E,F,G,H,I,J,K,L,M,N,O,P) \
  ( (unsigned long long)(A)        | ((unsigned long long)(B)<<4)  | \
    ((unsigned long long)(C)<<8)   | ((unsigned long long)(D)<<12) | \
    ((unsigned long long)(E)<<16)  | ((unsigned long long)(F)<<20) | \
    ((unsigned long long)(G)<<24)  | ((unsigned long long)(H)<<28) | \
    ((unsigned long long)(I)<<32)  | ((unsigned long long)(J)<<36) | \
    ((unsigned long long)(K)<<40)  | ((unsigned long long)(L)<<44) | \
    ((unsigned long long)(M)<<48)  | ((unsigned long long)(N)<<52) | \
    ((unsigned long long)(O)<<56)  | ((unsigned long long)(P)<<60) )
#define PKX(...) PK(__VA_ARGS__)

__device__ const unsigned long long c_ord64[8] = {
    PKX(ORD_Q0), PKX(ORD_Q1), PKX(ORD_Q2), PKX(ORD_Q3),
    PKX(ORD_Q4), PKX(ORD_Q5), PKX(ORD_Q6), PKX(ORD_Q7)
};

// ---------------------------------------------------------------------------
__global__ void tab_kernel()
{
    int a = threadIdx.x;
    if (a < NA) {
        const double PI = 3.14159265358979323846;
        double th = (double)a * (PI / 180.0);
        double irho = 227.0 / 180.0;   // (int(sqrt(160^2+160^2))+1)/180
        g_tab[a]      = cos(th) / irho;
        g_tab[NA + a] = sin(th) / irho;
    }
}

// ---------------------------------------------------------------------------
__global__ void build_idx_kernel()
{
    const int a = blockIdx.y;
    double tc = g_tab[a], ts = g_tab[NA + a];
    int p = blockIdx.x * 256 + threadIdx.x;
    int y = p / WW, x = p - y * WW;
    double v = __dadd_rn(__dmul_rn((double)(x - 80), tc),
                         __dmul_rn((double)(y - 80), ts));
    int r = (int)rint(v) + 90;
    r = min(NR - 1, max(0, r));
    g_idx[(size_t)a * PIX + p] = (unsigned char)r;
}

// ---------------------------------------------------------------------------
__global__ void transpose_kernel(const float* __restrict__ in)
{
    __shared__ float tile[32][33];
    int ar0 = blockIdx.x * 32;
    int nc0 = blockIdx.y * 32;
    int tx = threadIdx.x;
    int ty = threadIdx.y;
    #pragma unroll
    for (int i = ty; i < 32; i += 8) {
        int ar = ar0 + tx;
        if (ar < AR) tile[i][tx] = in[(size_t)(nc0 + i) * AR + ar];
    }
    __syncthreads();
    #pragma unroll
    for (int i = ty; i < 32; i += 8) {
        int ar = ar0 + i;
        if (ar < AR) g_T[(size_t)ar * NC + nc0 + tx] = tile[tx][i];
    }
}

// ---------------------------------------------------------------------------
// Kernel 3: main inverse-Hough.
//   CTA = 16x8 tile x 128 ch, 256 thr = 8 warps, 3 CTAs/SM target.
//   Warp = one 4x4 pixel block; lane = 4 consecutive channels.
//   EXACT sorted walk per angle (16 segments at true tan-theta
//   boundaries) -> loads = range+1 (minimum, ~3.6/angle/16px).
//   Record = 16 x 4-bit absolute window-relative nibbles (2 u32):
//   every step's address is INDEPENDENT (ad = nib*512 + sA); reload
//   predicate = nib change (rotating nibA/nibB). No serial chains.
//   Double-buffered cp.async staging, phase handled inside angle loop.
// ---------------------------------------------------------------------------
__device__ __forceinline__ void cp16(unsigned smem_addr, const void* gptr)
{
    asm volatile("cp.async.cg.shared.global [%0], [%1], 16;\n"
                 :: "r"(smem_addr), "l"(gptr));
}

__global__ void __launch_bounds__(TPB, 3) iht_main_kernel(float* __restrict__ out)
{
    __shared__ __align__(16) char sbuf[2][BUFB];     // 49152 B
    __shared__ uint2 sw2[8 * NA];                    // 11520 B
    __shared__ unsigned char sbase[192];

    const int tid = threadIdx.x;
    const int x0 = blockIdx.x * 16;
    const int y0 = blockIdx.y * 8;
    const int cz0 = blockIdx.z * 128;
    const int lane = tid & 31;
    const int w = tid >> 5;                          // warp = 4x4 block id

    // ---- per-angle window base (min over tile corners; affine) ----
    if (tid < NA) {
        const unsigned char* s = g_idx + (size_t)tid * PIX + y0 * WW + x0;
        int m = min(min((int)s[0], (int)s[15]),
                    min((int)s[7 * WW], (int)s[7 * WW + 15]));
        sbase[tid] = (unsigned char)min(m, NR - WR);
    }
    __syncthreads();

    // ---- staging (fixed span, double buffer) ----
    auto stage = [&](int f) {
        int a0 = f * PH;
        unsigned sd = (unsigned)__cvta_generic_to_shared(sbuf[f & 1]);
        #pragma unroll
        for (int it = 0; it < 6; it++) {
            int e = tid + it * TPB;                  // 1536 slots of 16B
            int s   = e >> 9;
            int rem = e & 511;
            int row = rem >> 5;
            int c   = rem & 31;
            int a = a0 + s;
            int r = (int)sbase[a] + row;
            cp16(sd + (e << 4),
                 g_T + ((size_t)a * NR + r) * NC + cz0 + c * 4);
        }
        asm volatile("cp.async.commit_group;\n" ::: "memory");
    };

    stage(0);

    // ---- build nibble records: sw2[blk*180+a] = 16 x 4b window-rel rho ----
    for (int i = tid; i < 8 * NA; i += TPB) {
        int blk = i & 7, a = i >> 3;
        // exact tan-theta classes (verified at integer degrees)
        int cls = a < 19 ? 0 : a < 27 ? 1 : a < 34 ? 2 : a < 45 ? 3
                : a < 57 ? 4 : a < 64 ? 5 : a < 72 ? 6 : a < 91 ? 7
                : a < 109 ? 8 : a < 117 ? 9 : a < 124 ? 10 : a < 136 ? 11
                : a < 147 ? 12 : a < 154 ? 13 : a < 162 ? 14 : 15;
        int mir = cls >= 8;
        unsigned long long ord = c_ord64[mir ? (15 - cls) : cls];
        const unsigned char* s = g_idx + (size_t)a * PIX
                                 + (y0 + 4 * (blk >> 2)) * WW + x0 + 4 * (blk & 3);
        unsigned t0 = *(const unsigned*)s;
        unsigned t1 = *(const unsigned*)(s + WW);
        unsigned t2 = *(const unsigned*)(s + 2 * WW);
        unsigned t3 = *(const unsigned*)(s + 3 * WW);
        int base = (int)sbase[a];
        unsigned wv0 = 0, wv1 = 0;
        #pragma unroll
        for (int k = 0; k < 16; k++) {
            int p = (int)((ord >> (4 * k)) & 15ull);
            if (mir) p = (3 - (p & 3)) | (p & 12);
            unsigned rowv = (p < 4) ? t0 : (p < 8) ? t1 : (p < 12) ? t2 : t3;
            unsigned rel = ((rowv >> (8 * (p & 3))) & 255u) - (unsigned)base;
            if (k < 8) wv0 |= rel << (4 * k);
            else       wv1 |= rel << (4 * (k - 8));
        }
        sw2[blk * NA + a] = make_uint2(wv0, wv1);
    }
    __syncthreads();

    // ---- accumulators: 16 px x 4 ch = 32 u64 (px = x + 4y) ----
    unsigned long long acc[32];
    #pragma unroll
    for (int i = 0; i < 32; i++) acc[i] = 0ull;

#define STEPF()                                                               \
    asm volatile("{\n\t .reg .u32 ad;\n\t"                                    \
        "bfe.u32 %2, %3, 0, 4;\n\t"                                           \
        "mad.lo.u32 ad, %2, 512, %4;\n\t"                                     \
        "ld.shared.v2.u64 {%0, %1}, [ad];\n\t"                                \
        "}"                                                                   \
        : "=l"(v0), "=l"(v1), "=r"(nibB)                                      \
        : "r"(wv0), "r"(sA))

#define STEPA(PXPREV, WREG, SH)                                               \
    asm volatile("{\n\t .reg .pred p;\n\t .reg .u32 ad;\n\t"                  \
        "add.rn.f32x2 %0, %0, %3;\n\t"                                        \
        "add.rn.f32x2 %1, %1, %4;\n\t"                                        \
        "bfe.u32 %2, %6, %7, 4;\n\t"                                          \
        "setp.ne.u32 p, %2, %5;\n\t"                                          \
        "mad.lo.u32 ad, %2, 512, %8;\n\t"                                     \
        "@p ld.shared.v2.u64 {%3, %4}, [ad];\n\t"                             \
        "}"                                                                   \
        : "+l"(acc[2*(PXPREV)]), "+l"(acc[2*(PXPREV)+1]),                     \
          "=r"(nibA), "+l"(v0), "+l"(v1)                                      \
        : "r"(nibB), "r"(WREG), "n"(SH), "r"(sA))

#define STEPB(PXPREV, WREG, SH)                                               \
    asm volatile("{\n\t .reg .pred p;\n\t .reg .u32 ad;\n\t"                  \
        "add.rn.f32x2 %0, %0, %3;\n\t"                                        \
        "add.rn.f32x2 %1, %1, %4;\n\t"                                        \
        "bfe.u32 %2, %6, %7, 4;\n\t"                                          \
        "setp.ne.u32 p, %2, %5;\n\t"                                          \
        "mad.lo.u32 ad, %2, 512, %8;\n\t"                                     \
        "@p ld.shared.v2.u64 {%3, %4}, [ad];\n\t"                             \
        "}"                                                                   \
        : "+l"(acc[2*(PXPREV)]), "+l"(acc[2*(PXPREV)+1]),                     \
          "=r"(nibB), "+l"(v0), "+l"(v1)                                      \
        : "r"(nibA), "r"(WREG), "n"(SH), "r"(sA))

#define FINAL(PX)                                                             \
    asm volatile("add.rn.f32x2 %0, %0, %1;" : "+l"(acc[2*(PX)])   : "l"(v0)); \
    asm volatile("add.rn.f32x2 %0, %0, %1;" : "+l"(acc[2*(PX)+1]) : "l"(v1))

#define DOANGLE(P0,P1,P2,P3,P4,P5,P6,P7,P8,P9,P10,P11,P12,P13,P14,P15)        \
    STEPF();                                                                  \
    STEPA(P0,  wv0,  4); STEPB(P1,  wv0,  8); STEPA(P2,  wv0, 12);            \
    STEPB(P3,  wv0, 16); STEPA(P4,  wv0, 20); STEPB(P5,  wv0, 24);            \
    STEPA(P6,  wv0, 28); STEPB(P7,  wv1,  0); STEPA(P8,  wv1,  4);            \
    STEPB(P9,  wv1,  8); STEPA(P10, wv1, 12); STEPB(P11, wv1, 16);            \
    STEPA(P12, wv1, 20); STEPB(P13, wv1, 24); STEPA(P14, wv1, 28);            \
    FINAL(P15)

#define DOSEG(A0, A1, P0,P1,P2,P3,P4,P5,P6,P7,P8,P9,P10,P11,P12,P13,P14,P15)  \
    for (int a = (A0); a < (A1); a++) {                                       \
        if (a % PH == 0) {                                                    \
            asm volatile("cp.async.wait_group 0;\n" ::: "memory");            \
            __syncthreads();                                                  \
            int fn = a / PH + 1;                                              \
            if (fn < NPHASE) stage(fn);                                       \
        }                                                                     \
        int f = a / PH;                                                       \
        unsigned sA = bufa0 + (unsigned)((f & 1) * BUFB)                      \
                      + (unsigned)((a - f * PH) * (WR * 512));                \
        uint2 wvp = sw2[swb + a];                                             \
        unsigned wv0 = wvp.x, wv1 = wvp.y;                                    \
        unsigned long long v0, v1;                                            \
        unsigned nibA, nibB;                                                  \
        DOANGLE(P0,P1,P2,P3,P4,P5,P6,P7,P8,P9,P10,P11,P12,P13,P14,P15);       \
    }

#define MM(P) ((3 - ((P) & 3)) | ((P) & 12))
#define DOSEGM(A0, A1, P0,P1,P2,P3,P4,P5,P6,P7,P8,P9,P10,P11,P12,P13,P14,P15) \
    DOSEG(A0, A1, MM(P0),MM(P1),MM(P2),MM(P3),MM(P4),MM(P5),MM(P6),MM(P7),    \
          MM(P8),MM(P9),MM(P10),MM(P11),MM(P12),MM(P13),MM(P14),MM(P15))
#define DOSEGX(A0, A1, ...)  DOSEG(A0, A1, __VA_ARGS__)
#define DOSEGMX(A0, A1, ...) DOSEGM(A0, A1, __VA_ARGS__)

    const unsigned swb = w * NA;
    unsigned bufa0 = (unsigned)__cvta_generic_to_shared(sbuf[0]) + (lane << 4);

    DOSEGX (  0,  19, ORD_Q0);
    DOSEGX ( 19,  27, ORD_Q1);
    DOSEGX ( 27,  34, ORD_Q2);
    DOSEGX ( 34,  45, ORD_Q3);
    DOSEGX ( 45,  57, ORD_Q4);
    DOSEGX ( 57,  64, ORD_Q5);
    DOSEGX ( 64,  72, ORD_Q6);
    DOSEGX ( 72,  91, ORD_Q7);
    DOSEGMX( 91, 109, ORD_Q7);
    DOSEGMX(109, 117, ORD_Q6);
    DOSEGMX(117, 124, ORD_Q5);
    DOSEGMX(124, 136, ORD_Q4);
    DOSEGMX(136, 147, ORD_Q3);
    DOSEGMX(147, 154, ORD_Q2);
    DOSEGMX(154, 162, ORD_Q1);
    DOSEGMX(162, 180, ORD_Q0);
#undef DOSEGX
#undef DOSEGMX
#undef DOSEGM
#undef DOSEG
#undef DOANGLE
#undef FINAL
#undef STEPB
#undef STEPA
#undef STEPF

    // ---- epilogue ----
    const int gx = x0 + 4 * (w & 3);
    const int gy = y0 + 4 * (w >> 2);
    const int c0 = cz0 + lane * 4;
    #pragma unroll
    for (int y = 0; y < 4; y++) {
        #pragma unroll
        for (int cc = 0; cc < 4; cc++) {
            int half = cc & 1, sel = cc >> 1;
            float4 o;
            unsigned long long s0 = acc[(0 + 4*y)*2 + sel];
            unsigned long long s1 = acc[(1 + 4*y)*2 + sel];
            unsigned long long s2 = acc[(2 + 4*y)*2 + sel];
            unsigned long long s3 = acc[(3 + 4*y)*2 + sel];
            o.x = __uint_as_float(half ? (unsigned)(s0 >> 32) : (unsigned)s0);
            o.y = __uint_as_float(half ? (unsigned)(s1 >> 32) : (unsigned)s1);
            o.z = __uint_as_float(half ? (unsigned)(s2 >> 32) : (unsigned)s2);
            o.w = __uint_as_float(half ? (unsigned)(s3 >> 32) : (unsigned)s3);
            *(float4*)(out + (size_t)(c0 + cc) * PIX + (gy + y) * WW + gx) = o;
        }
    }
}

// ---------------------------------------------------------------------------
extern "C" void kernel_launch(void* const* d_in, const int* in_sizes, int n_in,
                              void* d_out, int out_size)
{
    const float* hough = (const float*)d_in[0];
    float* out = (float*)d_out;

    tab_kernel<<<1, 256>>>();
    build_idx_kernel<<<dim3(PIX / 256, NA), 256>>>();
    transpose_kernel<<<dim3((AR + 31) / 32, NC / 32), dim3(32, 8)>>>(hough);
    iht_main_kernel<<<dim3(10, 20, 8), TPB>>>(out);
}

// round 15
// speedup vs baseline: 2.2970x; 2.2970x over previous
#include <cuda_runtime.h>
#include <cstdint>
#include <cstddef>

// Problem constants
#define NB   8
#define CB   128
#define NC   1024          // NB*CB
#define HH   160
#define WW   160
#define NA   180
#define NR   180
#define AR   (NA*NR)       // 32400
#define PIX  (HH*WW)       // 25600
#define WR   16            // staged rho-window rows (16x8 tile span <= 15)
#define PH   3             // angles per staging phase
#define NPHASE (NA/PH)     // 60
#define TPB  512
#define BUFB (PH*WR*512)   // 24576 B per buffer

// Scratch in __device__ globals (no allocation allowed)
__device__ float         g_T[(size_t)AR * NC];       // transposed: T[a][r][nc]
__device__ unsigned char g_idx[(size_t)NA * PIX];    // r index table [a][y][x]
__device__ double        g_tab[2 * NA];              // cos/irho, sin/irho

// sorted walk orders (8 px of a 4x2 block, px = x + 4y), packed 3b per slot
__device__ const unsigned c_ord[8] = {
    0u|(4u<<3)|(1u<<6)|(5u<<9)|(2u<<12)|(6u<<15)|(3u<<18)|(7u<<21),  // [0,45)
    0u|(1u<<3)|(4u<<6)|(2u<<9)|(5u<<12)|(3u<<15)|(6u<<18)|(7u<<21),  // [45,63)
    0u|(1u<<3)|(2u<<6)|(4u<<9)|(3u<<12)|(5u<<15)|(6u<<18)|(7u<<21),  // [63,72)
    0u|(1u<<3)|(2u<<6)|(3u<<9)|(4u<<12)|(5u<<15)|(6u<<18)|(7u<<21),  // [72,90)
    3u|(2u<<3)|(1u<<6)|(0u<<9)|(7u<<12)|(6u<<15)|(5u<<18)|(4u<<21),  // [90,108)
    3u|(2u<<3)|(1u<<6)|(7u<<9)|(0u<<12)|(6u<<15)|(5u<<18)|(4u<<21),  // [108,117)
    3u|(2u<<3)|(7u<<6)|(1u<<9)|(6u<<12)|(0u<<15)|(5u<<18)|(4u<<21),  // [117,135)
    3u|(7u<<3)|(2u<<6)|(6u<<9)|(1u<<12)|(5u<<15)|(0u<<18)|(4u<<21)   // [135,180)
};

// ---------------------------------------------------------------------------
// Kernel 0: trig table (fp64, once)
// ---------------------------------------------------------------------------
__global__ void tab_kernel()
{
    int a = threadIdx.x;
    if (a < NA) {
        const double PI = 3.14159265358979323846;
        double th = (double)a * (PI / 180.0);
        double irho = 227.0 / 180.0;   // (int(sqrt(160^2+160^2))+1)/180
        g_tab[a]      = cos(th) / irho;
        g_tab[NA + a] = sin(th) / irho;
    }
}

// ---------------------------------------------------------------------------
// Kernel 1: rho-index table (fp64 FMA-class ops only; matches numpy exactly)
// ---------------------------------------------------------------------------
__global__ void build_idx_kernel()
{
    const int a = blockIdx.y;
    double tc = g_tab[a], ts = g_tab[NA + a];
    int p = blockIdx.x * 256 + threadIdx.x;
    int y = p / WW, x = p - y * WW;
    double v = __dadd_rn(__dmul_rn((double)(x - 80), tc),
                         __dmul_rn((double)(y - 80), ts));
    int r = (int)rint(v) + 90;
    r = min(NR - 1, max(0, r));
    g_idx[(size_t)a * PIX + p] = (unsigned char)r;
}

// ---------------------------------------------------------------------------
// Kernel 2: vectorized transpose In[NC][AR] -> T[AR][NC].
//   Tile = 48 ar x 32 nc. Load: float4 along ar; store: float4 along nc,
//   128B-coalesced. Padded smem, conflict-free.
// ---------------------------------------------------------------------------
__global__ void __launch_bounds__(384) transpose_kernel(const float* __restrict__ in)
{
    __shared__ float tile[48][33];
    const int ar0 = blockIdx.x * 48;
    const int nc0 = blockIdx.y * 32;
    const int ty = threadIdx.x;          // 0..31 : nc within tile
    const int tx = threadIdx.y;          // 0..11 : group of 4 ar

    float4 v = *(const float4*)&in[(size_t)(nc0 + ty) * AR + ar0 + 4 * tx];
    tile[4 * tx + 0][ty] = v.x;
    tile[4 * tx + 1][ty] = v.y;
    tile[4 * tx + 2][ty] = v.z;
    tile[4 * tx + 3][ty] = v.w;
    __syncthreads();

    const int tid = ty + 32 * tx;        // 0..383
    const int i = tid >> 3;              // 0..47 : ar within tile
    const int j = tid & 7;               // 0..7  : group of 4 nc
    float4 o;
    o.x = tile[i][4 * j + 0];
    o.y = tile[i][4 * j + 1];
    o.z = tile[i][4 * j + 2];
    o.w = tile[i][4 * j + 3];
    *(float4*)&g_T[(size_t)(ar0 + i) * NC + nc0 + 4 * j] = o;
}

// ---------------------------------------------------------------------------
// Kernel 3: main inverse-Hough (R9, byte-identical — known 458 us).
//   CTA = 16x8 pixel tile x 128 ch, 512 thr = 16 warps, 2 CTAs/SM.
//   Warp = one 4x2 pixel block; lane = 4 consecutive channels.
//   Sorted-by-rho walk per angle class => loads = range+1 (minimum).
//   Double-buffered cp.async staging (3 angles x 16 rows x 512B).
// ---------------------------------------------------------------------------
__device__ __forceinline__ void cp16(unsigned smem_addr, const void* gptr)
{
    asm volatile("cp.async.cg.shared.global [%0], [%1], 16;\n"
                 :: "r"(smem_addr), "l"(gptr));
}

__global__ void __launch_bounds__(TPB, 2) iht_main_kernel(float* __restrict__ out)
{
    __shared__ __align__(16) char sbuf[2][BUFB];     // 49152 B
    __shared__ unsigned sw[16 * NA];                 // 11520 B
    __shared__ unsigned char sbase[192];

    const int tid = threadIdx.x;
    const int x0 = blockIdx.x * 16;
    const int y0 = blockIdx.y * 8;
    const int cz0 = blockIdx.z * 128;
    const int lane = tid & 31;
    const int w = tid >> 5;                          // warp = pixel block id

    // ---- per-angle window base (min over tile corners; affine => corners) ----
    if (tid < NA) {
        const unsigned char* s = g_idx + (size_t)tid * PIX + y0 * WW + x0;
        int m = min(min((int)s[0], (int)s[15]),
                    min((int)s[7 * WW], (int)s[7 * WW + 15]));
        sbase[tid] = (unsigned char)min(m, NR - WR);
    }
    __syncthreads();

    // ---- staging ----
    auto stage = [&](int f) {
        int a0 = f * PH;
        unsigned sd = (unsigned)__cvta_generic_to_shared(sbuf[f & 1]);
        #pragma unroll
        for (int it = 0; it < 3; it++) {
            int e = tid + it * TPB;                  // 1536 granules of 16B
            int s   = e >> 9;
            int rem = e & 511;
            int row = rem >> 5;
            int c   = rem & 31;
            int a = a0 + s;
            int r = (int)sbase[a] + row;
            cp16(sd + (e << 4),
                 g_T + ((size_t)a * NR + r) * NC + cz0 + c * 4);
        }
        asm volatile("cp.async.commit_group;\n" ::: "memory");
    };

    stage(0);

    // ---- build packed sorted-walk records: sw[blk*180 + a] ----
    // STRICT boundaries: must match the DOSEG consume ranges exactly
    // (0-44->0, 45-62->1, 63-71->2, 72-89->3, 90-107->4, 108-116->5,
    //  117-134->6, 135-179->7)
    for (int i = tid; i < 16 * NA; i += TPB) {
        int blk = i & 15, a = i >> 4;
        int cls = a < 45 ? 0 : a < 63 ? 1 : a < 72 ? 2 : a < 90 ? 3
                : a < 108 ? 4 : a < 117 ? 5 : a < 135 ? 6 : 7;
        unsigned ord = c_ord[cls];
        const unsigned char* s = g_idx + (size_t)a * PIX
                                 + (y0 + 2 * (blk >> 2)) * WW + x0 + 4 * (blk & 3);
        unsigned t0 = *(const unsigned*)s;           // y=0 row: px 0..3
        unsigned t1 = *(const unsigned*)(s + WW);    // y=1 row: px 4..7
        int p = ord & 7;
        int prev = (int)(((p < 4 ? t0 : t1) >> (8 * (p & 3))) & 255u);
        unsigned wv = (unsigned)(prev - (int)sbase[a]);
        #pragma unroll
        for (int k = 1; k < 8; k++) {
            p = (ord >> (3 * k)) & 7;
            int cur = (int)(((p < 4 ? t0 : t1) >> (8 * (p & 3))) & 255u);
            wv |= ((unsigned)((cur - prev) & 7)) << (5 + 3 * (k - 1));
            prev = cur;
        }
        sw[blk * NA + a] = wv;
    }
    __syncthreads();

    // ---- accumulators: 8 px x 4 ch = 16 u64 (px index = x + 4y) ----
    unsigned long long acc[16];
    #pragma unroll
    for (int i = 0; i < 16; i++) acc[i] = 0ull;

#define STEP0(PX)                                                             \
    asm volatile("{\n\t"                                                      \
        ".reg .u32 rr;\n\t"                                                   \
        "bfe.u32 rr, %5, 0, 5;\n\t"                                           \
        "mad.lo.u32 %4, rr, 512, %6;\n\t"                                     \
        "ld.shared.v2.u64 {%2, %3}, [%4];\n\t"                                \
        "add.rn.f32x2 %0, %0, %2;\n\t"                                        \
        "add.rn.f32x2 %1, %1, %3;\n\t"                                        \
        "}"                                                                   \
        : "+l"(acc[2*(PX)]), "+l"(acc[2*(PX)+1]),                             \
          "+l"(v0), "+l"(v1), "=r"(ad)                                        \
        : "r"(wv), "r"(sA))

#define STEPD(PX, K)                                                          \
    asm volatile("{\n\t"                                                      \
        ".reg .pred p;\n\t .reg .s32 d;\n\t"                                  \
        "bfe.s32 d, %5, %6, 3;\n\t"                                           \
        "setp.ne.s32 p, d, 0;\n\t"                                            \
        "mad.lo.s32 %4, d, 512, %4;\n\t"                                      \
        "@p ld.shared.v2.u64 {%2, %3}, [%4];\n\t"                             \
        "add.rn.f32x2 %0, %0, %2;\n\t"                                        \
        "add.rn.f32x2 %1, %1, %3;\n\t"                                        \
        "}"                                                                   \
        : "+l"(acc[2*(PX)]), "+l"(acc[2*(PX)+1]),                             \
          "+l"(v0), "+l"(v1), "+r"(ad)                                        \
        : "r"(wv), "n"(5 + 3*((K)-1)))

#define DOSEG(F0, F1, Q0,Q1,Q2,Q3,Q4,Q5,Q6,Q7)                                \
    for (int f = (F0); f < (F1); f++) {                                       \
        asm volatile("cp.async.wait_group 0;\n" ::: "memory");                \
        __syncthreads();                                                      \
        if (f + 1 < NPHASE) stage(f + 1);                                     \
        unsigned bufa = bufa0 + (unsigned)((f & 1) * BUFB);                   \
        _Pragma("unroll")                                                     \
        for (int s2 = 0; s2 < PH; s2++) {                                     \
            unsigned wv = sw[swb + f * PH + s2];                              \
            unsigned sA = bufa + (unsigned)(s2 * (WR * 512));                 \
            unsigned long long v0 = 0, v1 = 0;                                \
            unsigned ad;                                                      \
            STEP0(Q0);    STEPD(Q1,1); STEPD(Q2,2); STEPD(Q3,3);              \
            STEPD(Q4,4);  STEPD(Q5,5); STEPD(Q6,6); STEPD(Q7,7);              \
        }                                                                     \
    }

    const unsigned swb = w * NA;
    unsigned bufa0 = (unsigned)__cvta_generic_to_shared(sbuf[0]) + (lane << 4);

    DOSEG( 0, 15, 0,4,1,5,2,6,3,7);   // a 0-44
    DOSEG(15, 21, 0,1,4,2,5,3,6,7);   // a 45-62
    DOSEG(21, 24, 0,1,2,4,3,5,6,7);   // a 63-71
    DOSEG(24, 30, 0,1,2,3,4,5,6,7);   // a 72-89
    DOSEG(30, 36, 3,2,1,0,7,6,5,4);   // a 90-107
    DOSEG(36, 39, 3,2,1,7,0,6,5,4);   // a 108-116
    DOSEG(39, 45, 3,2,7,1,6,0,5,4);   // a 117-134
    DOSEG(45, 60, 3,7,2,6,1,5,0,4);   // a 135-179
#undef DOSEG
#undef STEPD
#undef STEP0

    // ---- epilogue: per ch, per row: float4 over the 4-wide block ----
    const int gx = x0 + 4 * (w & 3);
    const int gy = y0 + 2 * (w >> 2);
    const int c0 = cz0 + lane * 4;
    #pragma unroll
    for (int y = 0; y < 2; y++) {
        #pragma unroll
        for (int cc = 0; cc < 4; cc++) {
            int half = cc & 1, sel = cc >> 1;
            float4 o;
            unsigned long long s0 = acc[(0 + 4*y)*2 + sel];
            unsigned long long s1 = acc[(1 + 4*y)*2 + sel];
            unsigned long long s2 = acc[(2 + 4*y)*2 + sel];
            unsigned long long s3 = acc[(3 + 4*y)*2 + sel];
            o.x = __uint_as_float(half ? (unsigned)(s0 >> 32) : (unsigned)s0);
            o.y = __uint_as_float(half ? (unsigned)(s1 >> 32) : (unsigned)s1);
            o.z = __uint_as_float(half ? (unsigned)(s2 >> 32) : (unsigned)s2);
            o.w = __uint_as_float(half ? (unsigned)(s3 >> 32) : (unsigned)s3);
            *(float4*)(out + (size_t)(c0 + cc) * PIX + (gy + y) * WW + gx) = o;
        }
    }
}

// ---------------------------------------------------------------------------
extern "C" void kernel_launch(void* const* d_in, const int* in_sizes, int n_in,
                              void* d_out, int out_size)
{
    const float* hough = (const float*)d_in[0];
    float* out = (float*)d_out;

    tab_kernel<<<1, 256>>>();
    build_idx_kernel<<<dim3(PIX / 256, NA), 256>>>();
    transpose_kernel<<<dim3(AR / 48, NC / 32), dim3(32, 12)>>>(hough);
    iht_main_kernel<<<dim3(10, 20, 8), TPB>>>(out);
}